// round 13
// baseline (speedup 1.0000x reference)
#include <cuda_runtime.h>
#include <cuda_bf16.h>
#include <cstdint>
#include <math.h>

// ---------------- problem constants ----------------
#define CB   4
#define CT   5
#define CC   512
#define CHW  1024        // H*W
#define CBT  20          // B*T
#define CG   32
#define CPG  16
#define GEPS 1e-6f
#define TTC  (CT*CC)     // 2560 row stride of pixel-major temporal buffers
#define SCALE 0.04419417382415922f   // 512^-0.5
#define BUFSTR ((size_t)CBT*CC*CHW)  // per-tensor element stride in fused qkv buffer

// smem tile geometry (bytes): k-chunk = 32 bf16 = 64B rows  (R8 geometry)
#define RS0  80          // m/n-major tile row stride: 64B + 16B pad (128 rows)
#define RS1  272         // k-major tile row stride: 256B + 16B pad (32 rows)
#define SLAB 10240       // per-operand slab: max(128*80, 32*272)
#define STG_B (2*SLAB)   // 20480 per stage (A + B)
#define NSTAGE 4
#define SMEM_TOTAL (NSTAGE*STG_B)   // 81920

// ---------------- scratch (device globals) ----------------------------------
static __device__ __nv_bfloat16 g_wb [(size_t)8*CC*CC];        // 8 weights bf16
static __device__ __nv_bfloat16 g_hnb[BUFSTR];
static __device__ __nv_bfloat16 g_qkvb[3*BUFSTR];              // fused q/k/v
static __device__ __nv_bfloat16 g_attb[(size_t)CBT*CHW*CHW];
static __device__ __nv_bfloat16 g_hspb[BUFSTR];
static __device__ float g_attf[(size_t)CBT*CHW*CHW];
static __device__ float g_spatio[BUFSTR];
static __device__ float g_bias_s[3*CC];
static __device__ float g_bias_t[3*CC];

// ---------------- small helpers ---------------------------------------------
static __inline__ __device__ float warpSum(float v) {
    #pragma unroll
    for (int o = 16; o > 0; o >>= 1) v += __shfl_xor_sync(0xffffffffu, v, o);
    return v;
}
static __inline__ __device__ float warpMax(float v) {
    #pragma unroll
    for (int o = 16; o > 0; o >>= 1) v = fmaxf(v, __shfl_xor_sync(0xffffffffu, v, o));
    return v;
}
static __device__ __forceinline__ void mma_bf16(float* d, const uint32_t* a, const uint32_t* b) {
    asm volatile(
        "mma.sync.aligned.m16n8k16.row.col.f32.bf16.bf16.f32 "
        "{%0,%1,%2,%3}, {%4,%5,%6,%7}, {%8,%9}, {%0,%1,%2,%3};"
        : "+f"(d[0]), "+f"(d[1]), "+f"(d[2]), "+f"(d[3])
        : "r"(a[0]), "r"(a[1]), "r"(a[2]), "r"(a[3]), "r"(b[0]), "r"(b[1]));
}
static __device__ __forceinline__ void ldsm4(uint32_t& r0, uint32_t& r1, uint32_t& r2, uint32_t& r3, uint32_t a) {
    asm volatile("ldmatrix.sync.aligned.m8n8.x4.shared.b16 {%0,%1,%2,%3}, [%4];"
                 : "=r"(r0), "=r"(r1), "=r"(r2), "=r"(r3) : "r"(a));
}
static __device__ __forceinline__ void ldsm4t(uint32_t& r0, uint32_t& r1, uint32_t& r2, uint32_t& r3, uint32_t a) {
    asm volatile("ldmatrix.sync.aligned.m8n8.x4.trans.shared.b16 {%0,%1,%2,%3}, [%4];"
                 : "=r"(r0), "=r"(r1), "=r"(r2), "=r"(r3) : "r"(a));
}
static __device__ __forceinline__ void cp16(uint32_t dst, const void* src) {
    asm volatile("cp.async.cg.shared.global [%0], [%1], 16;" :: "r"(dst), "l"(src));
}
static __device__ __forceinline__ void cp_commit() {
    asm volatile("cp.async.commit_group;" ::: "memory");
}
template<int N> static __device__ __forceinline__ void cp_wait() {
    asm volatile("cp.async.wait_group %0;" :: "n"(N) : "memory");
}

// ---------------- bf16 m16n8k16 GEMM, ldmatrix + cp.async 4-stage (R8 core) --
// C[m,n] = alpha * sum_k Aop[m,k] * Bop[k,n]  (+bias[m]) (+resid)
//   TA=0: A gmem [m][k] (ld=lda)   TA=1: A gmem [k][m]
//   TB=0: B gmem [n][k] (ld=ldb)   TB=1: B gmem [k][n]
//   BMODE=1: B batch offset is pixel-major temporal layout
//   CMODE: 0 = C[bz*sC + m*N + n]
//          1 = pixel-major temporal C[n*TTC + m] (bf16)
//          2 = fused qkv split: C[(m>>9)*BUFSTR + bz*sC + (m&511)*N + n] (bf16)
//          3 = fused qkv split pixel-major (bf16)
//   OBF=1: output bf16, else fp32
template<int TA, int TB, int BMODE, int CMODE, int OBF>
__global__ __launch_bounds__(256, 2) void gemm_bf(
    const __nv_bfloat16* __restrict__ A, const __nv_bfloat16* __restrict__ B, void* __restrict__ Cvp,
    const float* __restrict__ bias, const float* __restrict__ resid,
    int N, int K, int lda, int ldb,
    long sA, long sB, long sC, long sR, float alpha)
{
    extern __shared__ char smem[];
    uint32_t sbase = (uint32_t)__cvta_generic_to_shared(smem);

    int tid = threadIdx.x, wid = tid >> 5, lane = tid & 31;
    int gq = lane >> 2, tg = lane & 3;
    int m0 = blockIdx.x * 128, n0 = blockIdx.y * 128, bz = blockIdx.z;
    int mw = (wid & 3) * 32, nw = (wid >> 2) * 64;

    size_t aoff = (size_t)bz * sA;
    size_t boff = BMODE ? (size_t)(bz / CT) * ((size_t)CHW * TTC) + (size_t)(bz % CT) * CC
                        : (size_t)bz * sB;

    float acc[2][8][4];
    #pragma unroll
    for (int mi = 0; mi < 2; mi++)
        #pragma unroll
        for (int ni = 0; ni < 8; ni++)
            #pragma unroll
            for (int c = 0; c < 4; c++) acc[mi][ni][c] = 0.f;

    auto issue = [&](int kc, int buf) {
        int k0 = kc << 5;
        uint32_t sa = sbase + buf * STG_B;
        uint32_t sb = sa + SLAB;
        #pragma unroll
        for (int i = 0; i < 2; i++) {
            int c = tid + i * 256;
            if (TA == 0) {
                int r = c >> 2, ch = c & 3;
                cp16(sa + (uint32_t)(r * RS0 + ch * 16),
                     A + aoff + (size_t)(m0 + r) * lda + k0 + ch * 8);
            } else {
                int r = c >> 4, ch = c & 15;
                cp16(sa + (uint32_t)(r * RS1 + ch * 16),
                     A + aoff + (size_t)(k0 + r) * lda + m0 + ch * 8);
            }
        }
        #pragma unroll
        for (int i = 0; i < 2; i++) {
            int c = tid + i * 256;
            if (TB == 0) {
                int r = c >> 2, ch = c & 3;
                cp16(sb + (uint32_t)(r * RS0 + ch * 16),
                     B + boff + (size_t)(n0 + r) * ldb + k0 + ch * 8);
            } else {
                int r = c >> 4, ch = c & 15;
                cp16(sb + (uint32_t)(r * RS1 + ch * 16),
                     B + boff + (size_t)(k0 + r) * ldb + n0 + ch * 8);
            }
        }
        cp_commit();
    };

    int NC = K >> 5;
    issue(0, 0); issue(1, 1); issue(2, 2);

    // ldmatrix lane decomposition
    int l7 = lane & 7;
    int sel8 = ((lane >> 3) & 1) * 8;
    int sel16 = (lane >> 4) * 8;

    for (int kc = 0; kc < NC; kc++) {
        cp_wait<2>();
        __syncthreads();
        if (kc + 3 < NC) issue(kc + 3, (kc + 3) & 3);

        uint32_t sa = sbase + (kc & 3) * STG_B;
        uint32_t sb = sa + SLAB;

        #pragma unroll
        for (int ks = 0; ks < 2; ks++) {
            int kb = ks * 16;
            uint32_t af[2][4];
            #pragma unroll
            for (int mi = 0; mi < 2; mi++) {
                if (TA == 0) {
                    uint32_t addr = sa + (uint32_t)((mw + mi * 16 + l7 + sel8) * RS0 + (kb + sel16) * 2);
                    ldsm4(af[mi][0], af[mi][1], af[mi][2], af[mi][3], addr);
                } else {
                    uint32_t addr = sa + (uint32_t)((kb + sel16 + l7) * RS1 + (mw + mi * 16 + sel8) * 2);
                    ldsm4t(af[mi][0], af[mi][1], af[mi][2], af[mi][3], addr);
                }
            }
            uint32_t bf[8][2];
            #pragma unroll
            for (int j2 = 0; j2 < 4; j2++) {
                uint32_t r0, r1, r2, r3;
                if (TB == 0) {
                    uint32_t addr = sb + (uint32_t)((nw + j2 * 16 + sel16 + l7) * RS0 + (kb + sel8) * 2);
                    ldsm4(r0, r1, r2, r3, addr);
                } else {
                    uint32_t addr = sb + (uint32_t)((kb + sel8 + l7) * RS1 + (nw + j2 * 16 + sel16) * 2);
                    ldsm4t(r0, r1, r2, r3, addr);
                }
                bf[j2 * 2 + 0][0] = r0; bf[j2 * 2 + 0][1] = r1;
                bf[j2 * 2 + 1][0] = r2; bf[j2 * 2 + 1][1] = r3;
            }
            #pragma unroll
            for (int mi = 0; mi < 2; mi++)
                #pragma unroll
                for (int ni = 0; ni < 8; ni++)
                    mma_bf16(acc[mi][ni], af[mi], bf[ni]);
        }
    }

    // ---- epilogue ----
    #pragma unroll
    for (int mi = 0; mi < 2; mi++) {
        #pragma unroll
        for (int half = 0; half < 2; half++) {
            int m = m0 + mw + mi * 16 + gq + half * 8;
            float bv = bias ? bias[m] : 0.f;
            if (CMODE == 0) {
                size_t cbase = (size_t)bz * sC + (size_t)m * N;
                size_t rbase = (size_t)bz * sR + (size_t)m * N;
                #pragma unroll
                for (int ni = 0; ni < 8; ni++) {
                    int n = n0 + nw + ni * 8 + tg * 2;
                    float v0 = acc[mi][ni][half * 2 + 0] * alpha + bv;
                    float v1 = acc[mi][ni][half * 2 + 1] * alpha + bv;
                    if (resid) {
                        v0 += resid[rbase + n];
                        v1 += resid[rbase + n + 1];
                    }
                    if (OBF) {
                        *(__nv_bfloat162*)((__nv_bfloat16*)Cvp + cbase + n) = __floats2bfloat162_rn(v0, v1);
                    } else {
                        *(float2*)((float*)Cvp + cbase + n) = make_float2(v0, v1);
                    }
                }
            } else if (CMODE == 2) {
                size_t cbase = (size_t)(m >> 9) * BUFSTR + (size_t)bz * sC + (size_t)(m & 511) * N;
                #pragma unroll
                for (int ni = 0; ni < 8; ni++) {
                    int n = n0 + nw + ni * 8 + tg * 2;
                    float v0 = acc[mi][ni][half * 2 + 0] * alpha + bv;
                    float v1 = acc[mi][ni][half * 2 + 1] * alpha + bv;
                    *(__nv_bfloat162*)((__nv_bfloat16*)Cvp + cbase + n) = __floats2bfloat162_rn(v0, v1);
                }
            } else {
                // CMODE 1/3: pixel-major temporal (bf16)
                int mb = (CMODE == 3) ? (m >> 9) : 0;
                int ml = (CMODE == 3) ? (m & 511) : m;
                size_t coff = (size_t)mb * BUFSTR
                            + (size_t)(bz / CT) * ((size_t)CHW * TTC) + (size_t)(bz % CT) * CC;
                __nv_bfloat16* Cb = (__nv_bfloat16*)Cvp;
                #pragma unroll
                for (int ni = 0; ni < 8; ni++) {
                    int n = n0 + nw + ni * 8 + tg * 2;
                    Cb[coff + (size_t)n * TTC + ml]       = __float2bfloat16_rn(acc[mi][ni][half * 2 + 0] * alpha + bv);
                    Cb[coff + (size_t)(n + 1) * TTC + ml] = __float2bfloat16_rn(acc[mi][ni][half * 2 + 1] * alpha + bv);
                }
            }
        }
    }
}

// ---------------- weight fp32 -> bf16 ----------------------------------------
__global__ __launch_bounds__(256) void cvt_weights(
    const float* w0, const float* w1, const float* w2, const float* w3,
    const float* w4, const float* w5, const float* w6, const float* w7,
    __nv_bfloat16* dst)
{
    int idx = blockIdx.x * 256 + threadIdx.x;
    int w = blockIdx.y;
    const float* src;
    switch (w) {
        case 0: src = w0; break; case 1: src = w1; break;
        case 2: src = w2; break; case 3: src = w3; break;
        case 4: src = w4; break; case 5: src = w5; break;
        case 6: src = w6; break; default: src = w7; break;
    }
    dst[(size_t)w * CC * CC + idx] = __float2bfloat16_rn(src[idx]);
}

// ---------------- stack biases -----------------------------------------------
__global__ void pack_bias(const float* b0, const float* b1, const float* b2,
                          const float* b3, const float* b4, const float* b5,
                          float* s, float* t)
{
    int i = blockIdx.x * 256 + threadIdx.x;     // 0..1535
    int w = i >> 9, j = i & 511;
    s[i] = (w == 0 ? b0 : (w == 1 ? b1 : b2))[j];
    t[i] = (w == 0 ? b3 : (w == 1 ? b4 : b5))[j];
}

// ---------------- GroupNorm (fp32 in -> bf16 out), float4 vectorized ---------
__global__ __launch_bounds__(256) void groupnorm_kernel(
    const float* __restrict__ x, __nv_bfloat16* __restrict__ out,
    const float* __restrict__ gamma, const float* __restrict__ beta)
{
    const int GSZ = CPG * CHW;                 // 16384 floats, contiguous
    const int G4  = GSZ / 4;                   // 4096 float4
    int n = blockIdx.x / CG, g = blockIdx.x % CG;
    size_t base = (size_t)n * CC * CHW + (size_t)g * GSZ;
    const float4* x4 = (const float4*)(x + base);
    int tid = threadIdx.x, lane = tid & 31, wid = tid >> 5;

    float s = 0.f, s2 = 0.f;
    for (int i = tid; i < G4; i += 256) {
        float4 v = x4[i];
        s  += (v.x + v.y) + (v.z + v.w);
        s2 += (v.x * v.x + v.y * v.y) + (v.z * v.z + v.w * v.w);
    }
    __shared__ float rs[8], rs2[8];
    s = warpSum(s); s2 = warpSum(s2);
    if (lane == 0) { rs[wid] = s; rs2[wid] = s2; }
    __syncthreads();
    if (tid == 0) {
        float S = 0.f, S2 = 0.f;
        #pragma unroll
        for (int w = 0; w < 8; w++) { S += rs[w]; S2 += rs2[w]; }
        rs[0] = S; rs2[0] = S2;
    }
    __syncthreads();
    float mu = rs[0] / (float)GSZ;
    float var = rs2[0] / (float)GSZ - mu * mu;
    float rstd = rsqrtf(var + GEPS);

    uint2* o8 = (uint2*)(out + base);
    for (int i = tid; i < G4; i += 256) {
        float4 v = x4[i];
        int c = g * CPG + ((i * 4) >> 10);     // all 4 lanes share the channel
        float ga = gamma[c] * rstd, be = beta[c] - mu * gamma[c] * rstd;
        union { __nv_bfloat162 h2[2]; uint2 u; } pk;
        pk.h2[0] = __floats2bfloat162_rn(v.x * ga + be, v.y * ga + be);
        pk.h2[1] = __floats2bfloat162_rn(v.z * ga + be, v.w * ga + be);
        o8[i] = pk.u;
    }
}

// ---------------- softmax (fp32 in -> bf16 out), row in registers ------------
__global__ __launch_bounds__(256) void softmax_kernel(
    const float* __restrict__ att, __nv_bfloat16* __restrict__ out)
{
    size_t row = (size_t)blockIdx.x * CHW;
    const float4* in4 = (const float4*)(att + row);
    __shared__ float red[8];
    int tid = threadIdx.x, lane = tid & 31, wid = tid >> 5;

    float4 v = in4[tid];                       // 256 thr x 4 = full row
    float mx = fmaxf(fmaxf(v.x, v.y), fmaxf(v.z, v.w));
    mx = warpMax(mx);
    if (lane == 0) red[wid] = mx;
    __syncthreads();
    if (tid == 0) {
        float m = red[0];
        #pragma unroll
        for (int w = 1; w < 8; w++) m = fmaxf(m, red[w]);
        red[0] = m;
    }
    __syncthreads();
    mx = red[0];
    __syncthreads();

    float e0 = __expf(v.x - mx), e1 = __expf(v.y - mx);
    float e2 = __expf(v.z - mx), e3 = __expf(v.w - mx);
    float s = (e0 + e1) + (e2 + e3);
    s = warpSum(s);
    if (lane == 0) red[wid] = s;
    __syncthreads();
    if (tid == 0) {
        float S = 0.f;
        #pragma unroll
        for (int w = 0; w < 8; w++) S += red[w];
        red[0] = S;
    }
    __syncthreads();
    float inv = 1.f / red[0];

    union { __nv_bfloat162 h2[2]; uint2 u; } pk;
    pk.h2[0] = __floats2bfloat162_rn(e0 * inv, e1 * inv);
    pk.h2[1] = __floats2bfloat162_rn(e2 * inv, e3 * inv);
    ((uint2*)(out + row))[tid] = pk.u;
}

// ---------------- temporal attention (bf16 pixel-major) ----------------------
__global__ __launch_bounds__(256) void temporal_attn_kernel(
    const __nv_bfloat16* __restrict__ q, const __nv_bfloat16* __restrict__ k,
    const __nv_bfloat16* __restrict__ v, __nv_bfloat16* __restrict__ o)
{
    size_t base = (size_t)blockIdx.x * TTC;
    int tid = threadIdx.x, lane = tid & 31;

    __shared__ float sacc[CT * CT];
    __shared__ float satt[CT][CT];
    if (tid < CT * CT) sacc[tid] = 0.f;

    float qr[2][CT], kr[2][CT], vr[2][CT];
    float acc[CT][CT] = {};

    #pragma unroll
    for (int r = 0; r < 2; r++) {
        int c = tid + r * 256;
        #pragma unroll
        for (int t = 0; t < CT; t++) {
            qr[r][t] = __bfloat162float(q[base + t * CC + c]);
            kr[r][t] = __bfloat162float(k[base + t * CC + c]);
            vr[r][t] = __bfloat162float(v[base + t * CC + c]);
        }
        #pragma unroll
        for (int t = 0; t < CT; t++)
            #pragma unroll
            for (int s = 0; s < CT; s++)
                acc[t][s] = fmaf(qr[r][t], kr[r][s], acc[t][s]);
    }
    __syncthreads();

    #pragma unroll
    for (int t = 0; t < CT; t++)
        #pragma unroll
        for (int s = 0; s < CT; s++) {
            float p = warpSum(acc[t][s]);
            if (lane == 0) atomicAdd(&sacc[t * CT + s], p);
        }
    __syncthreads();

    if (tid < CT) {
        float mx = -3.4e38f;
        #pragma unroll
        for (int s = 0; s < CT; s++) mx = fmaxf(mx, sacc[tid * CT + s] * SCALE);
        float sum = 0.f;
        #pragma unroll
        for (int s = 0; s < CT; s++) {
            float e = __expf(sacc[tid * CT + s] * SCALE - mx);
            satt[tid][s] = e;
            sum += e;
        }
        float inv = 1.f / sum;
        #pragma unroll
        for (int s = 0; s < CT; s++) satt[tid][s] *= inv;
    }
    __syncthreads();

    #pragma unroll
    for (int r = 0; r < 2; r++) {
        int c = tid + r * 256;
        #pragma unroll
        for (int t = 0; t < CT; t++) {
            float ov = 0.f;
            #pragma unroll
            for (int s = 0; s < CT; s++) ov = fmaf(satt[t][s], vr[r][s], ov);
            o[base + t * CC + c] = __float2bfloat16_rn(ov);
        }
    }
}

// ---------------- launch ----------------------------------------------------
extern "C" void kernel_launch(void* const* d_in, const int* in_sizes, int n_in,
                              void* d_out, int out_size)
{
    const float* x     = (const float*)d_in[0];
    const float* wq    = (const float*)d_in[1];
    const float* bq    = (const float*)d_in[2];
    const float* wk    = (const float*)d_in[3];
    const float* bk    = (const float*)d_in[4];
    const float* wv    = (const float*)d_in[5];
    const float* bv    = (const float*)d_in[6];
    const float* wo    = (const float*)d_in[7];
    const float* bo    = (const float*)d_in[8];
    const float* wqt   = (const float*)d_in[9];
    const float* bqt   = (const float*)d_in[10];
    const float* wkt   = (const float*)d_in[11];
    const float* bkt   = (const float*)d_in[12];
    const float* wvt   = (const float*)d_in[13];
    const float* bvt   = (const float*)d_in[14];
    const float* wot   = (const float*)d_in[15];
    const float* bot   = (const float*)d_in[16];
    const float* gamma_s = (const float*)d_in[17];
    const float* beta_s  = (const float*)d_in[18];
    const float* gamma_t = (const float*)d_in[19];
    const float* beta_t  = (const float*)d_in[20];
    float* out = (float*)d_out;

    __nv_bfloat16 *wb, *hnb, *qkvb, *attb, *hspb;
    float *attf, *spatio, *bias_s, *bias_t;
    cudaGetSymbolAddress((void**)&wb,    g_wb);
    cudaGetSymbolAddress((void**)&hnb,   g_hnb);
    cudaGetSymbolAddress((void**)&qkvb,  g_qkvb);
    cudaGetSymbolAddress((void**)&attb,  g_attb);
    cudaGetSymbolAddress((void**)&hspb,  g_hspb);
    cudaGetSymbolAddress((void**)&attf,  g_attf);
    cudaGetSymbolAddress((void**)&spatio, g_spatio);
    cudaGetSymbolAddress((void**)&bias_s, g_bias_s);
    cudaGetSymbolAddress((void**)&bias_t, g_bias_t);

    __nv_bfloat16 *qb = qkvb, *kb = qkvb + BUFSTR, *vb = qkvb + 2 * BUFSTR;

    cudaFuncSetAttribute(gemm_bf<0,1,0,2,1>, cudaFuncAttributeMaxDynamicSharedMemorySize, SMEM_TOTAL);
    cudaFuncSetAttribute(gemm_bf<1,1,0,0,0>, cudaFuncAttributeMaxDynamicSharedMemorySize, SMEM_TOTAL);
    cudaFuncSetAttribute(gemm_bf<0,0,0,0,1>, cudaFuncAttributeMaxDynamicSharedMemorySize, SMEM_TOTAL);
    cudaFuncSetAttribute(gemm_bf<0,1,0,0,0>, cudaFuncAttributeMaxDynamicSharedMemorySize, SMEM_TOTAL);
    cudaFuncSetAttribute(gemm_bf<0,1,0,3,1>, cudaFuncAttributeMaxDynamicSharedMemorySize, SMEM_TOTAL);
    cudaFuncSetAttribute(gemm_bf<0,0,1,0,0>, cudaFuncAttributeMaxDynamicSharedMemorySize, SMEM_TOTAL);

    const long SCHW = (long)CC * CHW;
    const long SATT = (long)CHW * CHW;
    const long WSZ  = (long)CC * CC;

    dim3 gridQKV(3 * CC / 128, CHW / 128, CBT);  // (12, 8, 20)
    dim3 gridConv(CC / 128, CHW / 128, CBT);     // (4, 8, 20)
    dim3 gridScores(CHW / 128, CHW / 128, CBT);  // (8, 8, 20)
    dim3 thr(256);

    // 0) weights -> bf16; stack biases
    cvt_weights<<<dim3(CC * CC / 256, 8), thr>>>(wq, wk, wv, wo, wqt, wkt, wvt, wot, wb);
    pack_bias<<<6, thr>>>(bq, bk, bv, bqt, bkt, bvt, bias_s, bias_t);
    const __nv_bfloat16 *wob = wb + 3 * WSZ, *wotb = wb + 7 * WSZ;

    // 1) spatial GroupNorm -> bf16
    groupnorm_kernel<<<CBT * CG, thr>>>(x, hnb, gamma_s, beta_s);

    // 2) fused q/k/v projection: A=[wq;wk;wv] [m][k], B=hn [k][n]; split bf16 out
    gemm_bf<0,1,0,2,1><<<gridQKV, thr, SMEM_TOTAL>>>(wb, hnb, qkvb, bias_s, nullptr,
                                CHW, CC, CC, CHW, 0, SCHW, SCHW, 0, 1.f);

    // 3) scores = scale * Q^T K : A=q [k][m], B=k [k][n]; fp32 out
    gemm_bf<1,1,0,0,0><<<gridScores, thr, SMEM_TOTAL>>>(qb, kb, attf, nullptr, nullptr,
                                CHW, CC, CHW, CHW, SCHW, SCHW, SATT, 0, SCALE);

    // 4) softmax over keys -> bf16
    softmax_kernel<<<CBT * CHW, thr>>>(attf, attb);

    // 5) hsp = V * Att^T : A=v [m][k], B=att [n][k]; bf16 out
    gemm_bf<0,0,0,0,1><<<gridConv, thr, SMEM_TOTAL>>>(vb, attb, hspb, nullptr, nullptr,
                                CHW, CHW, CHW, CHW, SCHW, SATT, SCHW, 0, 1.f);

    // 6) spatio = x + Wo*hsp + bo; fp32 out
    gemm_bf<0,1,0,0,0><<<gridConv, thr, SMEM_TOTAL>>>(wob, hspb, spatio, bo, x,
                                CHW, CC, CC, CHW, 0, SCHW, SCHW, SCHW, 1.f);

    // 7) temporal GroupNorm -> bf16
    groupnorm_kernel<<<CBT * CG, thr>>>(spatio, hnb, gamma_t, beta_t);

    // 8) fused temporal q/k/v, split pixel-major bf16 out
    gemm_bf<0,1,0,3,1><<<gridQKV, thr, SMEM_TOTAL>>>(wb + 4 * WSZ, hnb, qkvb, bias_t, nullptr,
                                CHW, CC, CC, CHW, 0, SCHW, SCHW, 0, 1.f);

    // 9) per-pixel temporal attention (htp into hspb, pixel-major bf16)
    temporal_attn_kernel<<<CB * CHW, thr>>>(qb, kb, vb, hspb);

    // 10) out = x + Wot*htp + bot : B=[n][k] rows via pixel-major (ldb=TTC); fp32 out
    gemm_bf<0,0,1,0,0><<<gridConv, thr, SMEM_TOTAL>>>(wotb, hspb, out, bot, x,
                                CHW, CC, CC, TTC, 0, 0, SCHW, SCHW, 1.f);
}

// round 14
// speedup vs baseline: 1.5112x; 1.5112x over previous
#include <cuda_runtime.h>
#include <cuda_bf16.h>
#include <cstdint>
#include <math.h>

// ---------------- problem constants ----------------
#define CB   4
#define CT   5
#define CC   512
#define CHW  1024        // H*W
#define CBT  20          // B*T
#define CG   32
#define CPG  16
#define GEPS 1e-6f
#define TTC  (CT*CC)     // 2560 row stride of pixel-major temporal buffers
#define SCALE 0.04419417382415922f   // 512^-0.5
#define BUFSTR ((size_t)CBT*CC*CHW)  // per-tensor element stride in fused qkv buffer

// smem tile geometry (bytes): k-chunk = 32 bf16 = 64B rows  (R8 geometry)
#define RS0  80          // m/n-major tile row stride: 64B + 16B pad (128 rows)
#define RS1  272         // k-major tile row stride: 256B + 16B pad (32 rows)
#define SLAB 10240       // per-operand slab: max(128*80, 32*272)
#define STG_B (2*SLAB)   // 20480 per stage (A + B)
#define NSTAGE 4
#define SMEM_TOTAL (NSTAGE*STG_B)   // 81920

// ---------------- scratch (device globals) ----------------------------------
static __device__ __nv_bfloat16 g_wb [(size_t)8*CC*CC];        // 8 weights bf16
static __device__ __nv_bfloat16 g_hnb[BUFSTR];
static __device__ __nv_bfloat16 g_qkvb[3*BUFSTR];              // fused q/k/v
static __device__ __nv_bfloat16 g_attb[(size_t)CBT*CHW*CHW];
static __device__ __nv_bfloat16 g_hspb[BUFSTR];
static __device__ float g_attf[(size_t)CBT*CHW*CHW];
static __device__ float g_spatio[BUFSTR];
static __device__ float g_bias_s[3*CC];
static __device__ float g_bias_t[3*CC];

// ---------------- small helpers ---------------------------------------------
static __inline__ __device__ float warpSum(float v) {
    #pragma unroll
    for (int o = 16; o > 0; o >>= 1) v += __shfl_xor_sync(0xffffffffu, v, o);
    return v;
}
static __inline__ __device__ float warpMax(float v) {
    #pragma unroll
    for (int o = 16; o > 0; o >>= 1) v = fmaxf(v, __shfl_xor_sync(0xffffffffu, v, o));
    return v;
}
static __device__ __forceinline__ void mma_bf16(float* d, const uint32_t* a, const uint32_t* b) {
    asm volatile(
        "mma.sync.aligned.m16n8k16.row.col.f32.bf16.bf16.f32 "
        "{%0,%1,%2,%3}, {%4,%5,%6,%7}, {%8,%9}, {%0,%1,%2,%3};"
        : "+f"(d[0]), "+f"(d[1]), "+f"(d[2]), "+f"(d[3])
        : "r"(a[0]), "r"(a[1]), "r"(a[2]), "r"(a[3]), "r"(b[0]), "r"(b[1]));
}
static __device__ __forceinline__ void ldsm4(uint32_t& r0, uint32_t& r1, uint32_t& r2, uint32_t& r3, uint32_t a) {
    asm volatile("ldmatrix.sync.aligned.m8n8.x4.shared.b16 {%0,%1,%2,%3}, [%4];"
                 : "=r"(r0), "=r"(r1), "=r"(r2), "=r"(r3) : "r"(a));
}
static __device__ __forceinline__ void ldsm4t(uint32_t& r0, uint32_t& r1, uint32_t& r2, uint32_t& r3, uint32_t a) {
    asm volatile("ldmatrix.sync.aligned.m8n8.x4.trans.shared.b16 {%0,%1,%2,%3}, [%4];"
                 : "=r"(r0), "=r"(r1), "=r"(r2), "=r"(r3) : "r"(a));
}
static __device__ __forceinline__ void cp16(uint32_t dst, const void* src) {
    asm volatile("cp.async.cg.shared.global [%0], [%1], 16;" :: "r"(dst), "l"(src));
}
static __device__ __forceinline__ void cp_commit() {
    asm volatile("cp.async.commit_group;" ::: "memory");
}
template<int N> static __device__ __forceinline__ void cp_wait() {
    asm volatile("cp.async.wait_group %0;" :: "n"(N) : "memory");
}

// ---------------- bf16 m16n8k16 GEMM, ldmatrix + cp.async 4-stage (R8 core) --
// C[m,n] = alpha * sum_k Aop[m,k] * Bop[k,n]  (+bias[m]) (+resid)
//   TA=0: A gmem [m][k] (ld=lda)   TA=1: A gmem [k][m]
//   TB=0: B gmem [n][k] (ld=ldb)   TB=1: B gmem [k][n]
//   BMODE=1: B batch offset is pixel-major temporal layout
//   CMODE: 0 = C[bz*sC + m*N + n]
//          1 = pixel-major temporal C[n*TTC + m] (bf16)
//          2 = fused qkv split: C[(m>>9)*BUFSTR + bz*sC + (m&511)*N + n] (bf16)
//          3 = fused qkv split pixel-major (bf16)
//   OBF=1: output bf16, else fp32
template<int TA, int TB, int BMODE, int CMODE, int OBF>
__global__ __launch_bounds__(256, 2) void gemm_bf(
    const __nv_bfloat16* __restrict__ A, const __nv_bfloat16* __restrict__ B, void* __restrict__ Cvp,
    const float* __restrict__ bias, const float* __restrict__ resid,
    int N, int K, int lda, int ldb,
    long sA, long sB, long sC, long sR, float alpha)
{
    extern __shared__ char smem[];
    uint32_t sbase = (uint32_t)__cvta_generic_to_shared(smem);

    int tid = threadIdx.x, wid = tid >> 5, lane = tid & 31;
    int gq = lane >> 2, tg = lane & 3;
    int m0 = blockIdx.x * 128, n0 = blockIdx.y * 128, bz = blockIdx.z;
    int mw = (wid & 3) * 32, nw = (wid >> 2) * 64;

    size_t aoff = (size_t)bz * sA;
    size_t boff = BMODE ? (size_t)(bz / CT) * ((size_t)CHW * TTC) + (size_t)(bz % CT) * CC
                        : (size_t)bz * sB;

    float acc[2][8][4];
    #pragma unroll
    for (int mi = 0; mi < 2; mi++)
        #pragma unroll
        for (int ni = 0; ni < 8; ni++)
            #pragma unroll
            for (int c = 0; c < 4; c++) acc[mi][ni][c] = 0.f;

    auto issue = [&](int kc, int buf) {
        int k0 = kc << 5;
        uint32_t sa = sbase + buf * STG_B;
        uint32_t sb = sa + SLAB;
        #pragma unroll
        for (int i = 0; i < 2; i++) {
            int c = tid + i * 256;
            if (TA == 0) {
                int r = c >> 2, ch = c & 3;
                cp16(sa + (uint32_t)(r * RS0 + ch * 16),
                     A + aoff + (size_t)(m0 + r) * lda + k0 + ch * 8);
            } else {
                int r = c >> 4, ch = c & 15;
                cp16(sa + (uint32_t)(r * RS1 + ch * 16),
                     A + aoff + (size_t)(k0 + r) * lda + m0 + ch * 8);
            }
        }
        #pragma unroll
        for (int i = 0; i < 2; i++) {
            int c = tid + i * 256;
            if (TB == 0) {
                int r = c >> 2, ch = c & 3;
                cp16(sb + (uint32_t)(r * RS0 + ch * 16),
                     B + boff + (size_t)(n0 + r) * ldb + k0 + ch * 8);
            } else {
                int r = c >> 4, ch = c & 15;
                cp16(sb + (uint32_t)(r * RS1 + ch * 16),
                     B + boff + (size_t)(k0 + r) * ldb + n0 + ch * 8);
            }
        }
        cp_commit();
    };

    int NC = K >> 5;
    issue(0, 0); issue(1, 1); issue(2, 2);

    // ldmatrix lane decomposition
    int l7 = lane & 7;
    int sel8 = ((lane >> 3) & 1) * 8;
    int sel16 = (lane >> 4) * 8;

    for (int kc = 0; kc < NC; kc++) {
        cp_wait<2>();
        __syncthreads();
        if (kc + 3 < NC) issue(kc + 3, (kc + 3) & 3);

        uint32_t sa = sbase + (kc & 3) * STG_B;
        uint32_t sb = sa + SLAB;

        #pragma unroll
        for (int ks = 0; ks < 2; ks++) {
            int kb = ks * 16;
            uint32_t af[2][4];
            #pragma unroll
            for (int mi = 0; mi < 2; mi++) {
                if (TA == 0) {
                    uint32_t addr = sa + (uint32_t)((mw + mi * 16 + l7 + sel8) * RS0 + (kb + sel16) * 2);
                    ldsm4(af[mi][0], af[mi][1], af[mi][2], af[mi][3], addr);
                } else {
                    uint32_t addr = sa + (uint32_t)((kb + sel16 + l7) * RS1 + (mw + mi * 16 + sel8) * 2);
                    ldsm4t(af[mi][0], af[mi][1], af[mi][2], af[mi][3], addr);
                }
            }
            uint32_t bf[8][2];
            #pragma unroll
            for (int j2 = 0; j2 < 4; j2++) {
                uint32_t r0, r1, r2, r3;
                if (TB == 0) {
                    uint32_t addr = sb + (uint32_t)((nw + j2 * 16 + sel16 + l7) * RS0 + (kb + sel8) * 2);
                    ldsm4(r0, r1, r2, r3, addr);
                } else {
                    uint32_t addr = sb + (uint32_t)((kb + sel8 + l7) * RS1 + (nw + j2 * 16 + sel16) * 2);
                    ldsm4t(r0, r1, r2, r3, addr);
                }
                bf[j2 * 2 + 0][0] = r0; bf[j2 * 2 + 0][1] = r1;
                bf[j2 * 2 + 1][0] = r2; bf[j2 * 2 + 1][1] = r3;
            }
            #pragma unroll
            for (int mi = 0; mi < 2; mi++)
                #pragma unroll
                for (int ni = 0; ni < 8; ni++)
                    mma_bf16(acc[mi][ni], af[mi], bf[ni]);
        }
    }

    // ---- epilogue ----
    #pragma unroll
    for (int mi = 0; mi < 2; mi++) {
        #pragma unroll
        for (int half = 0; half < 2; half++) {
            int m = m0 + mw + mi * 16 + gq + half * 8;
            float bv = bias ? bias[m] : 0.f;
            if (CMODE == 0) {
                size_t cbase = (size_t)bz * sC + (size_t)m * N;
                size_t rbase = (size_t)bz * sR + (size_t)m * N;
                #pragma unroll
                for (int ni = 0; ni < 8; ni++) {
                    int n = n0 + nw + ni * 8 + tg * 2;
                    float v0 = acc[mi][ni][half * 2 + 0] * alpha + bv;
                    float v1 = acc[mi][ni][half * 2 + 1] * alpha + bv;
                    if (resid) {
                        v0 += resid[rbase + n];
                        v1 += resid[rbase + n + 1];
                    }
                    if (OBF) {
                        *(__nv_bfloat162*)((__nv_bfloat16*)Cvp + cbase + n) = __floats2bfloat162_rn(v0, v1);
                    } else {
                        *(float2*)((float*)Cvp + cbase + n) = make_float2(v0, v1);
                    }
                }
            } else if (CMODE == 2) {
                size_t cbase = (size_t)(m >> 9) * BUFSTR + (size_t)bz * sC + (size_t)(m & 511) * N;
                #pragma unroll
                for (int ni = 0; ni < 8; ni++) {
                    int n = n0 + nw + ni * 8 + tg * 2;
                    float v0 = acc[mi][ni][half * 2 + 0] * alpha + bv;
                    float v1 = acc[mi][ni][half * 2 + 1] * alpha + bv;
                    *(__nv_bfloat162*)((__nv_bfloat16*)Cvp + cbase + n) = __floats2bfloat162_rn(v0, v1);
                }
            } else {
                // CMODE 1/3: pixel-major temporal (bf16)
                int mb = (CMODE == 3) ? (m >> 9) : 0;
                int ml = (CMODE == 3) ? (m & 511) : m;
                size_t coff = (size_t)mb * BUFSTR
                            + (size_t)(bz / CT) * ((size_t)CHW * TTC) + (size_t)(bz % CT) * CC;
                __nv_bfloat16* Cb = (__nv_bfloat16*)Cvp;
                #pragma unroll
                for (int ni = 0; ni < 8; ni++) {
                    int n = n0 + nw + ni * 8 + tg * 2;
                    Cb[coff + (size_t)n * TTC + ml]       = __float2bfloat16_rn(acc[mi][ni][half * 2 + 0] * alpha + bv);
                    Cb[coff + (size_t)(n + 1) * TTC + ml] = __float2bfloat16_rn(acc[mi][ni][half * 2 + 1] * alpha + bv);
                }
            }
        }
    }
}

// ---------------- weight fp32 -> bf16 ----------------------------------------
__global__ __launch_bounds__(256) void cvt_weights(
    const float* w0, const float* w1, const float* w2, const float* w3,
    const float* w4, const float* w5, const float* w6, const float* w7,
    __nv_bfloat16* dst)
{
    int idx = blockIdx.x * 256 + threadIdx.x;
    int w = blockIdx.y;
    const float* src;
    switch (w) {
        case 0: src = w0; break; case 1: src = w1; break;
        case 2: src = w2; break; case 3: src = w3; break;
        case 4: src = w4; break; case 5: src = w5; break;
        case 6: src = w6; break; default: src = w7; break;
    }
    dst[(size_t)w * CC * CC + idx] = __float2bfloat16_rn(src[idx]);
}

// ---------------- stack biases -----------------------------------------------
__global__ void pack_bias(const float* b0, const float* b1, const float* b2,
                          const float* b3, const float* b4, const float* b5,
                          float* s, float* t)
{
    int i = blockIdx.x * 256 + threadIdx.x;     // 0..1535
    int w = i >> 9, j = i & 511;
    s[i] = (w == 0 ? b0 : (w == 1 ? b1 : b2))[j];
    t[i] = (w == 0 ? b3 : (w == 1 ? b4 : b5))[j];
}

// ---------------- GroupNorm (fp32 in -> bf16 out), float4 vectorized ---------
__global__ __launch_bounds__(256) void groupnorm_kernel(
    const float* __restrict__ x, __nv_bfloat16* __restrict__ out,
    const float* __restrict__ gamma, const float* __restrict__ beta)
{
    const int GSZ = CPG * CHW;                 // 16384 floats, contiguous
    const int G4  = GSZ / 4;                   // 4096 float4
    int n = blockIdx.x / CG, g = blockIdx.x % CG;
    size_t base = (size_t)n * CC * CHW + (size_t)g * GSZ;
    const float4* x4 = (const float4*)(x + base);
    int tid = threadIdx.x, lane = tid & 31, wid = tid >> 5;

    float s = 0.f, s2 = 0.f;
    for (int i = tid; i < G4; i += 256) {
        float4 v = x4[i];
        s  += (v.x + v.y) + (v.z + v.w);
        s2 += (v.x * v.x + v.y * v.y) + (v.z * v.z + v.w * v.w);
    }
    __shared__ float rs[8], rs2[8];
    s = warpSum(s); s2 = warpSum(s2);
    if (lane == 0) { rs[wid] = s; rs2[wid] = s2; }
    __syncthreads();
    if (tid == 0) {
        float S = 0.f, S2 = 0.f;
        #pragma unroll
        for (int w = 0; w < 8; w++) { S += rs[w]; S2 += rs2[w]; }
        rs[0] = S; rs2[0] = S2;
    }
    __syncthreads();
    float mu = rs[0] / (float)GSZ;
    float var = rs2[0] / (float)GSZ - mu * mu;
    float rstd = rsqrtf(var + GEPS);

    uint2* o8 = (uint2*)(out + base);
    for (int i = tid; i < G4; i += 256) {
        float4 v = x4[i];
        int c = g * CPG + ((i * 4) >> 10);     // all 4 lanes share the channel
        float ga = gamma[c] * rstd, be = beta[c] - mu * gamma[c] * rstd;
        union { __nv_bfloat162 h2[2]; uint2 u; } pk;
        pk.h2[0] = __floats2bfloat162_rn(v.x * ga + be, v.y * ga + be);
        pk.h2[1] = __floats2bfloat162_rn(v.z * ga + be, v.w * ga + be);
        o8[i] = pk.u;
    }
}

// ---------------- softmax (fp32 in -> bf16 out), row in registers ------------
__global__ __launch_bounds__(256) void softmax_kernel(
    const float* __restrict__ att, __nv_bfloat16* __restrict__ out)
{
    size_t row = (size_t)blockIdx.x * CHW;
    const float4* in4 = (const float4*)(att + row);
    __shared__ float red[8];
    int tid = threadIdx.x, lane = tid & 31, wid = tid >> 5;

    float4 v = in4[tid];                       // 256 thr x 4 = full row
    float mx = fmaxf(fmaxf(v.x, v.y), fmaxf(v.z, v.w));
    mx = warpMax(mx);
    if (lane == 0) red[wid] = mx;
    __syncthreads();
    if (tid == 0) {
        float m = red[0];
        #pragma unroll
        for (int w = 1; w < 8; w++) m = fmaxf(m, red[w]);
        red[0] = m;
    }
    __syncthreads();
    mx = red[0];
    __syncthreads();

    float e0 = __expf(v.x - mx), e1 = __expf(v.y - mx);
    float e2 = __expf(v.z - mx), e3 = __expf(v.w - mx);
    float s = (e0 + e1) + (e2 + e3);
    s = warpSum(s);
    if (lane == 0) red[wid] = s;
    __syncthreads();
    if (tid == 0) {
        float S = 0.f;
        #pragma unroll
        for (int w = 0; w < 8; w++) S += red[w];
        red[0] = S;
    }
    __syncthreads();
    float inv = 1.f / red[0];

    union { __nv_bfloat162 h2[2]; uint2 u; } pk;
    pk.h2[0] = __floats2bfloat162_rn(e0 * inv, e1 * inv);
    pk.h2[1] = __floats2bfloat162_rn(e2 * inv, e3 * inv);
    ((uint2*)(out + row))[tid] = pk.u;
}

// ---------------- temporal attention (bf16 pixel-major) ----------------------
__global__ __launch_bounds__(256) void temporal_attn_kernel(
    const __nv_bfloat16* __restrict__ q, const __nv_bfloat16* __restrict__ k,
    const __nv_bfloat16* __restrict__ v, __nv_bfloat16* __restrict__ o)
{
    size_t base = (size_t)blockIdx.x * TTC;
    int tid = threadIdx.x, lane = tid & 31;

    __shared__ float sacc[CT * CT];
    __shared__ float satt[CT][CT];
    if (tid < CT * CT) sacc[tid] = 0.f;

    float qr[2][CT], kr[2][CT], vr[2][CT];
    float acc[CT][CT] = {};

    #pragma unroll
    for (int r = 0; r < 2; r++) {
        int c = tid + r * 256;
        #pragma unroll
        for (int t = 0; t < CT; t++) {
            qr[r][t] = __bfloat162float(q[base + t * CC + c]);
            kr[r][t] = __bfloat162float(k[base + t * CC + c]);
            vr[r][t] = __bfloat162float(v[base + t * CC + c]);
        }
        #pragma unroll
        for (int t = 0; t < CT; t++)
            #pragma unroll
            for (int s = 0; s < CT; s++)
                acc[t][s] = fmaf(qr[r][t], kr[r][s], acc[t][s]);
    }
    __syncthreads();

    #pragma unroll
    for (int t = 0; t < CT; t++)
        #pragma unroll
        for (int s = 0; s < CT; s++) {
            float p = warpSum(acc[t][s]);
            if (lane == 0) atomicAdd(&sacc[t * CT + s], p);
        }
    __syncthreads();

    if (tid < CT) {
        float mx = -3.4e38f;
        #pragma unroll
        for (int s = 0; s < CT; s++) mx = fmaxf(mx, sacc[tid * CT + s] * SCALE);
        float sum = 0.f;
        #pragma unroll
        for (int s = 0; s < CT; s++) {
            float e = __expf(sacc[tid * CT + s] * SCALE - mx);
            satt[tid][s] = e;
            sum += e;
        }
        float inv = 1.f / sum;
        #pragma unroll
        for (int s = 0; s < CT; s++) satt[tid][s] *= inv;
    }
    __syncthreads();

    #pragma unroll
    for (int r = 0; r < 2; r++) {
        int c = tid + r * 256;
        #pragma unroll
        for (int t = 0; t < CT; t++) {
            float ov = 0.f;
            #pragma unroll
            for (int s = 0; s < CT; s++) ov = fmaf(satt[t][s], vr[r][s], ov);
            o[base + t * CC + c] = __float2bfloat16_rn(ov);
        }
    }
}

// ---------------- launch ----------------------------------------------------
extern "C" void kernel_launch(void* const* d_in, const int* in_sizes, int n_in,
                              void* d_out, int out_size)
{
    const float* x     = (const float*)d_in[0];
    const float* wq    = (const float*)d_in[1];
    const float* bq    = (const float*)d_in[2];
    const float* wk    = (const float*)d_in[3];
    const float* bk    = (const float*)d_in[4];
    const float* wv    = (const float*)d_in[5];
    const float* bv    = (const float*)d_in[6];
    const float* wo    = (const float*)d_in[7];
    const float* bo    = (const float*)d_in[8];
    const float* wqt   = (const float*)d_in[9];
    const float* bqt   = (const float*)d_in[10];
    const float* wkt   = (const float*)d_in[11];
    const float* bkt   = (const float*)d_in[12];
    const float* wvt   = (const float*)d_in[13];
    const float* bvt   = (const float*)d_in[14];
    const float* wot   = (const float*)d_in[15];
    const float* bot   = (const float*)d_in[16];
    const float* gamma_s = (const float*)d_in[17];
    const float* beta_s  = (const float*)d_in[18];
    const float* gamma_t = (const float*)d_in[19];
    const float* beta_t  = (const float*)d_in[20];
    float* out = (float*)d_out;

    __nv_bfloat16 *wb, *hnb, *qkvb, *attb, *hspb;
    float *attf, *spatio, *bias_s, *bias_t;
    cudaGetSymbolAddress((void**)&wb,    g_wb);
    cudaGetSymbolAddress((void**)&hnb,   g_hnb);
    cudaGetSymbolAddress((void**)&qkvb,  g_qkvb);
    cudaGetSymbolAddress((void**)&attb,  g_attb);
    cudaGetSymbolAddress((void**)&hspb,  g_hspb);
    cudaGetSymbolAddress((void**)&attf,  g_attf);
    cudaGetSymbolAddress((void**)&spatio, g_spatio);
    cudaGetSymbolAddress((void**)&bias_s, g_bias_s);
    cudaGetSymbolAddress((void**)&bias_t, g_bias_t);

    __nv_bfloat16 *qb = qkvb, *kb = qkvb + BUFSTR, *vb = qkvb + 2 * BUFSTR;

    cudaFuncSetAttribute(gemm_bf<0,1,0,2,1>, cudaFuncAttributeMaxDynamicSharedMemorySize, SMEM_TOTAL);
    cudaFuncSetAttribute(gemm_bf<1,1,0,0,0>, cudaFuncAttributeMaxDynamicSharedMemorySize, SMEM_TOTAL);
    cudaFuncSetAttribute(gemm_bf<0,0,0,0,1>, cudaFuncAttributeMaxDynamicSharedMemorySize, SMEM_TOTAL);
    cudaFuncSetAttribute(gemm_bf<0,1,0,0,0>, cudaFuncAttributeMaxDynamicSharedMemorySize, SMEM_TOTAL);
    cudaFuncSetAttribute(gemm_bf<0,1,0,3,1>, cudaFuncAttributeMaxDynamicSharedMemorySize, SMEM_TOTAL);
    cudaFuncSetAttribute(gemm_bf<0,0,1,0,0>, cudaFuncAttributeMaxDynamicSharedMemorySize, SMEM_TOTAL);

    const long SCHW = (long)CC * CHW;
    const long SATT = (long)CHW * CHW;
    const long WSZ  = (long)CC * CC;

    dim3 gridQKV(3 * CC / 128, CHW / 128, CBT);  // (12, 8, 20)
    dim3 gridConv(CC / 128, CHW / 128, CBT);     // (4, 8, 20)
    dim3 gridScores(CHW / 128, CHW / 128, CBT);  // (8, 8, 20)
    dim3 thr(256);

    // 0) weights -> bf16; stack biases
    cvt_weights<<<dim3(CC * CC / 256, 8), thr>>>(wq, wk, wv, wo, wqt, wkt, wvt, wot, wb);
    pack_bias<<<6, thr>>>(bq, bk, bv, bqt, bkt, bvt, bias_s, bias_t);
    const __nv_bfloat16 *wob = wb + 3 * WSZ, *wotb = wb + 7 * WSZ;

    // 1) spatial GroupNorm -> bf16
    groupnorm_kernel<<<CBT * CG, thr>>>(x, hnb, gamma_s, beta_s);

    // 2) fused q/k/v projection: A=[wq;wk;wv] [m][k], B=hn [k][n]; split bf16 out
    gemm_bf<0,1,0,2,1><<<gridQKV, thr, SMEM_TOTAL>>>(wb, hnb, qkvb, bias_s, nullptr,
                                CHW, CC, CC, CHW, 0, SCHW, SCHW, 0, 1.f);

    // 3) scores = scale * Q^T K : A=q [k][m], B=k [k][n]; fp32 out
    gemm_bf<1,1,0,0,0><<<gridScores, thr, SMEM_TOTAL>>>(qb, kb, attf, nullptr, nullptr,
                                CHW, CC, CHW, CHW, SCHW, SCHW, SATT, 0, SCALE);

    // 4) softmax over keys -> bf16
    softmax_kernel<<<CBT * CHW, thr>>>(attf, attb);

    // 5) hsp = V * Att^T : A=v [m][k], B=att [n][k]; bf16 out
    gemm_bf<0,0,0,0,1><<<gridConv, thr, SMEM_TOTAL>>>(vb, attb, hspb, nullptr, nullptr,
                                CHW, CHW, CHW, CHW, SCHW, SATT, SCHW, 0, 1.f);

    // 6) spatio = x + Wo*hsp + bo; fp32 out
    gemm_bf<0,1,0,0,0><<<gridConv, thr, SMEM_TOTAL>>>(wob, hspb, spatio, bo, x,
                                CHW, CC, CC, CHW, 0, SCHW, SCHW, SCHW, 1.f);

    // 7) temporal GroupNorm -> bf16
    groupnorm_kernel<<<CBT * CG, thr>>>(spatio, hnb, gamma_t, beta_t);

    // 8) fused temporal q/k/v, split pixel-major bf16 out
    gemm_bf<0,1,0,3,1><<<gridQKV, thr, SMEM_TOTAL>>>(wb + 4 * WSZ, hnb, qkvb, bias_t, nullptr,
                                CHW, CC, CC, CHW, 0, SCHW, SCHW, 0, 1.f);

    // 9) per-pixel temporal attention (htp into hspb, pixel-major bf16)
    temporal_attn_kernel<<<CB * CHW, thr>>>(qb, kb, vb, hspb);

    // 10) out = x + Wot*htp + bot : B=[n][k] rows via pixel-major (ldb=TTC); fp32 out
    gemm_bf<0,0,1,0,0><<<gridConv, thr, SMEM_TOTAL>>>(wotb, hspb, out, bot, x,
                                CHW, CC, CC, TTC, 0, 0, SCHW, SCHW, 1.f);
}

// round 15
// speedup vs baseline: 1.5249x; 1.0091x over previous
#include <cuda_runtime.h>
#include <cuda_bf16.h>
#include <cstdint>
#include <math.h>

// ---------------- problem constants ----------------
#define CB   4
#define CT   5
#define CC   512
#define CHW  1024        // H*W
#define CBT  20          // B*T
#define CG   32
#define CPG  16
#define GEPS 1e-6f
#define TTC  (CT*CC)     // 2560 row stride of pixel-major temporal buffers
#define SCALE 0.04419417382415922f   // 512^-0.5
#define BUFSTR ((size_t)CBT*CC*CHW)  // per-tensor element stride in fused qkv buffer

// smem tile geometry (bytes): k-chunk = 32 bf16 = 64B rows  (R8 geometry)
#define RS0  80          // m/n-major tile row stride: 64B + 16B pad (128 rows)
#define RS1  272         // k-major tile row stride: 256B + 16B pad (32 rows)
#define SLAB 10240       // per-operand slab: max(128*80, 32*272)
#define STG_B (2*SLAB)   // 20480 per stage (A + B)
#define NSTAGE 4
#define SMEM_TOTAL (NSTAGE*STG_B)   // 81920

// ---------------- scratch (device globals) ----------------------------------
static __device__ __nv_bfloat16 g_wb [(size_t)8*CC*CC];        // 8 weights bf16
static __device__ __nv_bfloat16 g_hnb[BUFSTR];
static __device__ __nv_bfloat16 g_qkvb[3*BUFSTR];              // fused q/k/v
static __device__ __nv_bfloat16 g_attb[(size_t)CBT*CHW*CHW];
static __device__ __nv_bfloat16 g_hspb[BUFSTR];
static __device__ float g_attf[(size_t)CBT*CHW*CHW];
static __device__ float g_spatio[BUFSTR];
static __device__ float g_bias_s[3*CC];
static __device__ float g_bias_t[3*CC];

// ---------------- small helpers ---------------------------------------------
static __inline__ __device__ float warpSum(float v) {
    #pragma unroll
    for (int o = 16; o > 0; o >>= 1) v += __shfl_xor_sync(0xffffffffu, v, o);
    return v;
}
static __inline__ __device__ float warpMax(float v) {
    #pragma unroll
    for (int o = 16; o > 0; o >>= 1) v = fmaxf(v, __shfl_xor_sync(0xffffffffu, v, o));
    return v;
}
static __device__ __forceinline__ void mma_bf16(float* d, const uint32_t* a, const uint32_t* b) {
    asm volatile(
        "mma.sync.aligned.m16n8k16.row.col.f32.bf16.bf16.f32 "
        "{%0,%1,%2,%3}, {%4,%5,%6,%7}, {%8,%9}, {%0,%1,%2,%3};"
        : "+f"(d[0]), "+f"(d[1]), "+f"(d[2]), "+f"(d[3])
        : "r"(a[0]), "r"(a[1]), "r"(a[2]), "r"(a[3]), "r"(b[0]), "r"(b[1]));
}
static __device__ __forceinline__ void ldsm4(uint32_t& r0, uint32_t& r1, uint32_t& r2, uint32_t& r3, uint32_t a) {
    asm volatile("ldmatrix.sync.aligned.m8n8.x4.shared.b16 {%0,%1,%2,%3}, [%4];"
                 : "=r"(r0), "=r"(r1), "=r"(r2), "=r"(r3) : "r"(a));
}
static __device__ __forceinline__ void ldsm4t(uint32_t& r0, uint32_t& r1, uint32_t& r2, uint32_t& r3, uint32_t a) {
    asm volatile("ldmatrix.sync.aligned.m8n8.x4.trans.shared.b16 {%0,%1,%2,%3}, [%4];"
                 : "=r"(r0), "=r"(r1), "=r"(r2), "=r"(r3) : "r"(a));
}
static __device__ __forceinline__ void cp16(uint32_t dst, const void* src) {
    asm volatile("cp.async.cg.shared.global [%0], [%1], 16;" :: "r"(dst), "l"(src));
}
static __device__ __forceinline__ void cp_commit() {
    asm volatile("cp.async.commit_group;" ::: "memory");
}
template<int N> static __device__ __forceinline__ void cp_wait() {
    asm volatile("cp.async.wait_group %0;" :: "n"(N) : "memory");
}

// ---------------- bf16 m16n8k16 GEMM, ldmatrix + cp.async 4-stage ------------
// Fragment-pipelined mainloop: B ping-pong prefetch at j2-group granularity,
// next-ks A/B prefetched during the last j2 group, so LDSM overlaps MMA.
// C[m,n] = alpha * sum_k Aop[m,k] * Bop[k,n]  (+bias[m]) (+resid)
//   TA=0: A gmem [m][k] (ld=lda)   TA=1: A gmem [k][m]
//   TB=0: B gmem [n][k] (ld=ldb)   TB=1: B gmem [k][n]
//   BMODE=1: B batch offset is pixel-major temporal layout
//   CMODE: 0 = C[bz*sC + m*N + n]
//          1 = pixel-major temporal C[n*TTC + m] (bf16)
//          2 = fused qkv split: C[(m>>9)*BUFSTR + bz*sC + (m&511)*N + n] (bf16)
//          3 = fused qkv split pixel-major (bf16)
//   OBF=1: output bf16, else fp32
template<int TA, int TB, int BMODE, int CMODE, int OBF>
__global__ __launch_bounds__(256, 2) void gemm_bf(
    const __nv_bfloat16* __restrict__ A, const __nv_bfloat16* __restrict__ B, void* __restrict__ Cvp,
    const float* __restrict__ bias, const float* __restrict__ resid,
    int N, int K, int lda, int ldb,
    long sA, long sB, long sC, long sR, float alpha)
{
    extern __shared__ char smem[];
    uint32_t sbase = (uint32_t)__cvta_generic_to_shared(smem);

    int tid = threadIdx.x, wid = tid >> 5, lane = tid & 31;
    int gq = lane >> 2, tg = lane & 3;
    int m0 = blockIdx.x * 128, n0 = blockIdx.y * 128, bz = blockIdx.z;
    int mw = (wid & 3) * 32, nw = (wid >> 2) * 64;

    size_t aoff = (size_t)bz * sA;
    size_t boff = BMODE ? (size_t)(bz / CT) * ((size_t)CHW * TTC) + (size_t)(bz % CT) * CC
                        : (size_t)bz * sB;

    float acc[2][8][4];
    #pragma unroll
    for (int mi = 0; mi < 2; mi++)
        #pragma unroll
        for (int ni = 0; ni < 8; ni++)
            #pragma unroll
            for (int c = 0; c < 4; c++) acc[mi][ni][c] = 0.f;

    auto issue = [&](int kc, int buf) {
        int k0 = kc << 5;
        uint32_t sa = sbase + buf * STG_B;
        uint32_t sb = sa + SLAB;
        #pragma unroll
        for (int i = 0; i < 2; i++) {
            int c = tid + i * 256;
            if (TA == 0) {
                int r = c >> 2, ch = c & 3;
                cp16(sa + (uint32_t)(r * RS0 + ch * 16),
                     A + aoff + (size_t)(m0 + r) * lda + k0 + ch * 8);
            } else {
                int r = c >> 4, ch = c & 15;
                cp16(sa + (uint32_t)(r * RS1 + ch * 16),
                     A + aoff + (size_t)(k0 + r) * lda + m0 + ch * 8);
            }
        }
        #pragma unroll
        for (int i = 0; i < 2; i++) {
            int c = tid + i * 256;
            if (TB == 0) {
                int r = c >> 2, ch = c & 3;
                cp16(sb + (uint32_t)(r * RS0 + ch * 16),
                     B + boff + (size_t)(n0 + r) * ldb + k0 + ch * 8);
            } else {
                int r = c >> 4, ch = c & 15;
                cp16(sb + (uint32_t)(r * RS1 + ch * 16),
                     B + boff + (size_t)(k0 + r) * ldb + n0 + ch * 8);
            }
        }
        cp_commit();
    };

    int NC = K >> 5;
    issue(0, 0); issue(1, 1); issue(2, 2);

    // ldmatrix lane decomposition
    int l7 = lane & 7;
    int sel8 = ((lane >> 3) & 1) * 8;
    int sel16 = (lane >> 4) * 8;

    // fragment ping-pong buffers
    uint32_t afb[2][2][4];   // [ks][mi][4]
    uint32_t bfb[2][4];      // [pp][4]

    auto ldA = [&](uint32_t sa, int kb, uint32_t (*af)[4]) {
        #pragma unroll
        for (int mi = 0; mi < 2; mi++) {
            if (TA == 0) {
                uint32_t addr = sa + (uint32_t)((mw + mi * 16 + l7 + sel8) * RS0 + (kb + sel16) * 2);
                ldsm4(af[mi][0], af[mi][1], af[mi][2], af[mi][3], addr);
            } else {
                uint32_t addr = sa + (uint32_t)((kb + sel16 + l7) * RS1 + (mw + mi * 16 + sel8) * 2);
                ldsm4t(af[mi][0], af[mi][1], af[mi][2], af[mi][3], addr);
            }
        }
    };
    auto ldB = [&](uint32_t sb, int kb, int j2, uint32_t* b4) {
        if (TB == 0) {
            uint32_t addr = sb + (uint32_t)((nw + j2 * 16 + sel16 + l7) * RS0 + (kb + sel8) * 2);
            ldsm4(b4[0], b4[1], b4[2], b4[3], addr);
        } else {
            uint32_t addr = sb + (uint32_t)((kb + sel8 + l7) * RS1 + (nw + j2 * 16 + sel16) * 2);
            ldsm4t(b4[0], b4[1], b4[2], b4[3], addr);
        }
    };

    for (int kc = 0; kc < NC; kc++) {
        cp_wait<2>();
        __syncthreads();
        if (kc + 3 < NC) issue(kc + 3, (kc + 3) & 3);

        uint32_t sa = sbase + (kc & 3) * STG_B;
        uint32_t sb = sa + SLAB;

        // preamble: first A (ks0) + first B group
        ldA(sa, 0, afb[0]);
        ldB(sb, 0, 0, bfb[0]);

        #pragma unroll
        for (int ks = 0; ks < 2; ks++) {
            int kb = ks * 16;
            #pragma unroll
            for (int t = 0; t < 4; t++) {
                const int pp = t & 1;
                // prefetch during this group's MMA burst
                if (t < 3) {
                    ldB(sb, kb, t + 1, bfb[pp ^ 1]);
                } else if (ks == 0) {
                    ldA(sa, 16, afb[1]);
                    ldB(sb, 16, 0, bfb[pp ^ 1]);
                }
                uint32_t b0[2] = { bfb[pp][0], bfb[pp][1] };
                uint32_t b1[2] = { bfb[pp][2], bfb[pp][3] };
                mma_bf16(acc[0][t * 2 + 0], afb[ks][0], b0);
                mma_bf16(acc[0][t * 2 + 1], afb[ks][0], b1);
                mma_bf16(acc[1][t * 2 + 0], afb[ks][1], b0);
                mma_bf16(acc[1][t * 2 + 1], afb[ks][1], b1);
            }
        }
    }

    // ---- epilogue ----
    #pragma unroll
    for (int mi = 0; mi < 2; mi++) {
        #pragma unroll
        for (int half = 0; half < 2; half++) {
            int m = m0 + mw + mi * 16 + gq + half * 8;
            float bv = bias ? bias[m] : 0.f;
            if (CMODE == 0) {
                size_t cbase = (size_t)bz * sC + (size_t)m * N;
                size_t rbase = (size_t)bz * sR + (size_t)m * N;
                #pragma unroll
                for (int ni = 0; ni < 8; ni++) {
                    int n = n0 + nw + ni * 8 + tg * 2;
                    float v0 = acc[mi][ni][half * 2 + 0] * alpha + bv;
                    float v1 = acc[mi][ni][half * 2 + 1] * alpha + bv;
                    if (resid) {
                        v0 += resid[rbase + n];
                        v1 += resid[rbase + n + 1];
                    }
                    if (OBF) {
                        *(__nv_bfloat162*)((__nv_bfloat16*)Cvp + cbase + n) = __floats2bfloat162_rn(v0, v1);
                    } else {
                        *(float2*)((float*)Cvp + cbase + n) = make_float2(v0, v1);
                    }
                }
            } else if (CMODE == 2) {
                size_t cbase = (size_t)(m >> 9) * BUFSTR + (size_t)bz * sC + (size_t)(m & 511) * N;
                #pragma unroll
                for (int ni = 0; ni < 8; ni++) {
                    int n = n0 + nw + ni * 8 + tg * 2;
                    float v0 = acc[mi][ni][half * 2 + 0] * alpha + bv;
                    float v1 = acc[mi][ni][half * 2 + 1] * alpha + bv;
                    *(__nv_bfloat162*)((__nv_bfloat16*)Cvp + cbase + n) = __floats2bfloat162_rn(v0, v1);
                }
            } else {
                // CMODE 1/3: pixel-major temporal (bf16)
                int mb = (CMODE == 3) ? (m >> 9) : 0;
                int ml = (CMODE == 3) ? (m & 511) : m;
                size_t coff = (size_t)mb * BUFSTR
                            + (size_t)(bz / CT) * ((size_t)CHW * TTC) + (size_t)(bz % CT) * CC;
                __nv_bfloat16* Cb = (__nv_bfloat16*)Cvp;
                #pragma unroll
                for (int ni = 0; ni < 8; ni++) {
                    int n = n0 + nw + ni * 8 + tg * 2;
                    Cb[coff + (size_t)n * TTC + ml]       = __float2bfloat16_rn(acc[mi][ni][half * 2 + 0] * alpha + bv);
                    Cb[coff + (size_t)(n + 1) * TTC + ml] = __float2bfloat16_rn(acc[mi][ni][half * 2 + 1] * alpha + bv);
                }
            }
        }
    }
}

// ---------------- weight fp32 -> bf16 ----------------------------------------
__global__ __launch_bounds__(256) void cvt_weights(
    const float* w0, const float* w1, const float* w2, const float* w3,
    const float* w4, const float* w5, const float* w6, const float* w7,
    __nv_bfloat16* dst)
{
    int idx = blockIdx.x * 256 + threadIdx.x;
    int w = blockIdx.y;
    const float* src;
    switch (w) {
        case 0: src = w0; break; case 1: src = w1; break;
        case 2: src = w2; break; case 3: src = w3; break;
        case 4: src = w4; break; case 5: src = w5; break;
        case 6: src = w6; break; default: src = w7; break;
    }
    dst[(size_t)w * CC * CC + idx] = __float2bfloat16_rn(src[idx]);
}

// ---------------- stack biases -----------------------------------------------
__global__ void pack_bias(const float* b0, const float* b1, const float* b2,
                          const float* b3, const float* b4, const float* b5,
                          float* s, float* t)
{
    int i = blockIdx.x * 256 + threadIdx.x;     // 0..1535
    int w = i >> 9, j = i & 511;
    s[i] = (w == 0 ? b0 : (w == 1 ? b1 : b2))[j];
    t[i] = (w == 0 ? b3 : (w == 1 ? b4 : b5))[j];
}

// ---------------- GroupNorm (fp32 in -> bf16 out), float4 vectorized ---------
__global__ __launch_bounds__(256) void groupnorm_kernel(
    const float* __restrict__ x, __nv_bfloat16* __restrict__ out,
    const float* __restrict__ gamma, const float* __restrict__ beta)
{
    const int GSZ = CPG * CHW;                 // 16384 floats, contiguous
    const int G4  = GSZ / 4;                   // 4096 float4
    int n = blockIdx.x / CG, g = blockIdx.x % CG;
    size_t base = (size_t)n * CC * CHW + (size_t)g * GSZ;
    const float4* x4 = (const float4*)(x + base);
    int tid = threadIdx.x, lane = tid & 31, wid = tid >> 5;

    float s = 0.f, s2 = 0.f;
    for (int i = tid; i < G4; i += 256) {
        float4 v = x4[i];
        s  += (v.x + v.y) + (v.z + v.w);
        s2 += (v.x * v.x + v.y * v.y) + (v.z * v.z + v.w * v.w);
    }
    __shared__ float rs[8], rs2[8];
    s = warpSum(s); s2 = warpSum(s2);
    if (lane == 0) { rs[wid] = s; rs2[wid] = s2; }
    __syncthreads();
    if (tid == 0) {
        float S = 0.f, S2 = 0.f;
        #pragma unroll
        for (int w = 0; w < 8; w++) { S += rs[w]; S2 += rs2[w]; }
        rs[0] = S; rs2[0] = S2;
    }
    __syncthreads();
    float mu = rs[0] / (float)GSZ;
    float var = rs2[0] / (float)GSZ - mu * mu;
    float rstd = rsqrtf(var + GEPS);

    uint2* o8 = (uint2*)(out + base);
    for (int i = tid; i < G4; i += 256) {
        float4 v = x4[i];
        int c = g * CPG + ((i * 4) >> 10);     // all 4 lanes share the channel
        float ga = gamma[c] * rstd, be = beta[c] - mu * gamma[c] * rstd;
        union { __nv_bfloat162 h2[2]; uint2 u; } pk;
        pk.h2[0] = __floats2bfloat162_rn(v.x * ga + be, v.y * ga + be);
        pk.h2[1] = __floats2bfloat162_rn(v.z * ga + be, v.w * ga + be);
        o8[i] = pk.u;
    }
}

// ---------------- softmax (fp32 in -> bf16 out), row in registers ------------
__global__ __launch_bounds__(256) void softmax_kernel(
    const float* __restrict__ att, __nv_bfloat16* __restrict__ out)
{
    size_t row = (size_t)blockIdx.x * CHW;
    const float4* in4 = (const float4*)(att + row);
    __shared__ float red[8];
    int tid = threadIdx.x, lane = tid & 31, wid = tid >> 5;

    float4 v = in4[tid];                       // 256 thr x 4 = full row
    float mx = fmaxf(fmaxf(v.x, v.y), fmaxf(v.z, v.w));
    mx = warpMax(mx);
    if (lane == 0) red[wid] = mx;
    __syncthreads();
    if (tid == 0) {
        float m = red[0];
        #pragma unroll
        for (int w = 1; w < 8; w++) m = fmaxf(m, red[w]);
        red[0] = m;
    }
    __syncthreads();
    mx = red[0];
    __syncthreads();

    float e0 = __expf(v.x - mx), e1 = __expf(v.y - mx);
    float e2 = __expf(v.z - mx), e3 = __expf(v.w - mx);
    float s = (e0 + e1) + (e2 + e3);
    s = warpSum(s);
    if (lane == 0) red[wid] = s;
    __syncthreads();
    if (tid == 0) {
        float S = 0.f;
        #pragma unroll
        for (int w = 0; w < 8; w++) S += red[w];
        red[0] = S;
    }
    __syncthreads();
    float inv = 1.f / red[0];

    union { __nv_bfloat162 h2[2]; uint2 u; } pk;
    pk.h2[0] = __floats2bfloat162_rn(e0 * inv, e1 * inv);
    pk.h2[1] = __floats2bfloat162_rn(e2 * inv, e3 * inv);
    ((uint2*)(out + row))[tid] = pk.u;
}

// ---------------- temporal attention (bf16 pixel-major) ----------------------
__global__ __launch_bounds__(256) void temporal_attn_kernel(
    const __nv_bfloat16* __restrict__ q, const __nv_bfloat16* __restrict__ k,
    const __nv_bfloat16* __restrict__ v, __nv_bfloat16* __restrict__ o)
{
    size_t base = (size_t)blockIdx.x * TTC;
    int tid = threadIdx.x, lane = tid & 31;

    __shared__ float sacc[CT * CT];
    __shared__ float satt[CT][CT];
    if (tid < CT * CT) sacc[tid] = 0.f;

    float qr[2][CT], kr[2][CT], vr[2][CT];
    float acc[CT][CT] = {};

    #pragma unroll
    for (int r = 0; r < 2; r++) {
        int c = tid + r * 256;
        #pragma unroll
        for (int t = 0; t < CT; t++) {
            qr[r][t] = __bfloat162float(q[base + t * CC + c]);
            kr[r][t] = __bfloat162float(k[base + t * CC + c]);
            vr[r][t] = __bfloat162float(v[base + t * CC + c]);
        }
        #pragma unroll
        for (int t = 0; t < CT; t++)
            #pragma unroll
            for (int s = 0; s < CT; s++)
                acc[t][s] = fmaf(qr[r][t], kr[r][s], acc[t][s]);
    }
    __syncthreads();

    #pragma unroll
    for (int t = 0; t < CT; t++)
        #pragma unroll
        for (int s = 0; s < CT; s++) {
            float p = warpSum(acc[t][s]);
            if (lane == 0) atomicAdd(&sacc[t * CT + s], p);
        }
    __syncthreads();

    if (tid < CT) {
        float mx = -3.4e38f;
        #pragma unroll
        for (int s = 0; s < CT; s++) mx = fmaxf(mx, sacc[tid * CT + s] * SCALE);
        float sum = 0.f;
        #pragma unroll
        for (int s = 0; s < CT; s++) {
            float e = __expf(sacc[tid * CT + s] * SCALE - mx);
            satt[tid][s] = e;
            sum += e;
        }
        float inv = 1.f / sum;
        #pragma unroll
        for (int s = 0; s < CT; s++) satt[tid][s] *= inv;
    }
    __syncthreads();

    #pragma unroll
    for (int r = 0; r < 2; r++) {
        int c = tid + r * 256;
        #pragma unroll
        for (int t = 0; t < CT; t++) {
            float ov = 0.f;
            #pragma unroll
            for (int s = 0; s < CT; s++) ov = fmaf(satt[t][s], vr[r][s], ov);
            o[base + t * CC + c] = __float2bfloat16_rn(ov);
        }
    }
}

// ---------------- launch ----------------------------------------------------
extern "C" void kernel_launch(void* const* d_in, const int* in_sizes, int n_in,
                              void* d_out, int out_size)
{
    const float* x     = (const float*)d_in[0];
    const float* wq    = (const float*)d_in[1];
    const float* bq    = (const float*)d_in[2];
    const float* wk    = (const float*)d_in[3];
    const float* bk    = (const float*)d_in[4];
    const float* wv    = (const float*)d_in[5];
    const float* bv    = (const float*)d_in[6];
    const float* wo    = (const float*)d_in[7];
    const float* bo    = (const float*)d_in[8];
    const float* wqt   = (const float*)d_in[9];
    const float* bqt   = (const float*)d_in[10];
    const float* wkt   = (const float*)d_in[11];
    const float* bkt   = (const float*)d_in[12];
    const float* wvt   = (const float*)d_in[13];
    const float* bvt   = (const float*)d_in[14];
    const float* wot   = (const float*)d_in[15];
    const float* bot   = (const float*)d_in[16];
    const float* gamma_s = (const float*)d_in[17];
    const float* beta_s  = (const float*)d_in[18];
    const float* gamma_t = (const float*)d_in[19];
    const float* beta_t  = (const float*)d_in[20];
    float* out = (float*)d_out;

    __nv_bfloat16 *wb, *hnb, *qkvb, *attb, *hspb;
    float *attf, *spatio, *bias_s, *bias_t;
    cudaGetSymbolAddress((void**)&wb,    g_wb);
    cudaGetSymbolAddress((void**)&hnb,   g_hnb);
    cudaGetSymbolAddress((void**)&qkvb,  g_qkvb);
    cudaGetSymbolAddress((void**)&attb,  g_attb);
    cudaGetSymbolAddress((void**)&hspb,  g_hspb);
    cudaGetSymbolAddress((void**)&attf,  g_attf);
    cudaGetSymbolAddress((void**)&spatio, g_spatio);
    cudaGetSymbolAddress((void**)&bias_s, g_bias_s);
    cudaGetSymbolAddress((void**)&bias_t, g_bias_t);

    __nv_bfloat16 *qb = qkvb, *kb = qkvb + BUFSTR, *vb = qkvb + 2 * BUFSTR;

    cudaFuncSetAttribute(gemm_bf<0,1,0,2,1>, cudaFuncAttributeMaxDynamicSharedMemorySize, SMEM_TOTAL);
    cudaFuncSetAttribute(gemm_bf<1,1,0,0,0>, cudaFuncAttributeMaxDynamicSharedMemorySize, SMEM_TOTAL);
    cudaFuncSetAttribute(gemm_bf<0,0,0,0,1>, cudaFuncAttributeMaxDynamicSharedMemorySize, SMEM_TOTAL);
    cudaFuncSetAttribute(gemm_bf<0,1,0,0,0>, cudaFuncAttributeMaxDynamicSharedMemorySize, SMEM_TOTAL);
    cudaFuncSetAttribute(gemm_bf<0,1,0,3,1>, cudaFuncAttributeMaxDynamicSharedMemorySize, SMEM_TOTAL);
    cudaFuncSetAttribute(gemm_bf<0,0,1,0,0>, cudaFuncAttributeMaxDynamicSharedMemorySize, SMEM_TOTAL);

    const long SCHW = (long)CC * CHW;
    const long SATT = (long)CHW * CHW;
    const long WSZ  = (long)CC * CC;

    dim3 gridQKV(3 * CC / 128, CHW / 128, CBT);  // (12, 8, 20)
    dim3 gridConv(CC / 128, CHW / 128, CBT);     // (4, 8, 20)
    dim3 gridScores(CHW / 128, CHW / 128, CBT);  // (8, 8, 20)
    dim3 thr(256);

    // 0) weights -> bf16; stack biases
    cvt_weights<<<dim3(CC * CC / 256, 8), thr>>>(wq, wk, wv, wo, wqt, wkt, wvt, wot, wb);
    pack_bias<<<6, thr>>>(bq, bk, bv, bqt, bkt, bvt, bias_s, bias_t);
    const __nv_bfloat16 *wob = wb + 3 * WSZ, *wotb = wb + 7 * WSZ;

    // 1) spatial GroupNorm -> bf16
    groupnorm_kernel<<<CBT * CG, thr>>>(x, hnb, gamma_s, beta_s);

    // 2) fused q/k/v projection: A=[wq;wk;wv] [m][k], B=hn [k][n]; split bf16 out
    gemm_bf<0,1,0,2,1><<<gridQKV, thr, SMEM_TOTAL>>>(wb, hnb, qkvb, bias_s, nullptr,
                                CHW, CC, CC, CHW, 0, SCHW, SCHW, 0, 1.f);

    // 3) scores = scale * Q^T K : A=q [k][m], B=k [k][n]; fp32 out
    gemm_bf<1,1,0,0,0><<<gridScores, thr, SMEM_TOTAL>>>(qb, kb, attf, nullptr, nullptr,
                                CHW, CC, CHW, CHW, SCHW, SCHW, SATT, 0, SCALE);

    // 4) softmax over keys -> bf16
    softmax_kernel<<<CBT * CHW, thr>>>(attf, attb);

    // 5) hsp = V * Att^T : A=v [m][k], B=att [n][k]; bf16 out
    gemm_bf<0,0,0,0,1><<<gridConv, thr, SMEM_TOTAL>>>(vb, attb, hspb, nullptr, nullptr,
                                CHW, CHW, CHW, CHW, SCHW, SATT, SCHW, 0, 1.f);

    // 6) spatio = x + Wo*hsp + bo; fp32 out
    gemm_bf<0,1,0,0,0><<<gridConv, thr, SMEM_TOTAL>>>(wob, hspb, spatio, bo, x,
                                CHW, CC, CC, CHW, 0, SCHW, SCHW, SCHW, 1.f);

    // 7) temporal GroupNorm -> bf16
    groupnorm_kernel<<<CBT * CG, thr>>>(spatio, hnb, gamma_t, beta_t);

    // 8) fused temporal q/k/v, split pixel-major bf16 out
    gemm_bf<0,1,0,3,1><<<gridQKV, thr, SMEM_TOTAL>>>(wb + 4 * WSZ, hnb, qkvb, bias_t, nullptr,
                                CHW, CC, CC, CHW, 0, SCHW, SCHW, 0, 1.f);

    // 9) per-pixel temporal attention (htp into hspb, pixel-major bf16)
    temporal_attn_kernel<<<CB * CHW, thr>>>(qb, kb, vb, hspb);

    // 10) out = x + Wot*htp + bot : B=[n][k] rows via pixel-major (ldb=TTC); fp32 out
    gemm_bf<0,0,1,0,0><<<gridConv, thr, SMEM_TOTAL>>>(wotb, hspb, out, bot, x,
                                CHW, CC, CC, TTC, 0, 0, SCHW, SCHW, 1.f);
}